// round 1
// baseline (speedup 1.0000x reference)
#include <cuda_runtime.h>

#define NN 256
#define LL 256
#define BB 16384

// ---------------- scratch (__device__ globals: no allocation) ----------------
__device__ float2 g_DG[LL * NN];   // diag[l][n]
__device__ float2 g_OP[LL * NN];   // off[l][n^1] stored at [l][n] (partner coeff for output n)
__device__ float4 g_WG[NN * NN];   // W[k][n] = (wr, wi, -wi, wr)

// packed f32x2 FMA: d(lo,hi) += a(lo,hi)*b(lo,hi)
#define FMA_F32X2(d, a, b) \
    asm("fma.rn.f32x2 %0, %1, %2, %0;" : "+l"(d) : "l"(a), "l"(b))

__device__ __forceinline__ float2 cmul(float2 a, float2 b) {
    return make_float2(a.x * b.x - a.y * b.y, a.x * b.y + a.y * b.x);
}

// ---------------- kernel 1: per-layer MZI coefficients ----------------
// diag[n] = epsl[n]   * 0.25 * (2*ipsl[n] - ipsl[n+1] - ipsl[n-1])
// off[n]  = epsl[n-1] * 0.25i * (2*ipsl[n] + ipsl[n+1] + ipsl[n-1])
__global__ void coeff_kernel(const float* __restrict__ theta,
                             const float* __restrict__ phi) {
    int l = blockIdx.x;
    int n = threadIdx.x;

    const float* th = theta + l * (NN / 2);
    const float* ph = phi + l * (NN / 2);

    auto ipsl = [&](int k) -> float2 {
        k &= (NN - 1);
        float ang = 0.5f * th[k >> 1];
        if (k & 1) ang = -ang;
        float s, c;
        sincosf(ang, &s, &c);
        return make_float2(c, s);
    };

    float2 p0 = ipsl(n - 1);
    float2 p1 = ipsl(n);
    float2 p2 = ipsl(n + 1);

    float2 v = make_float2(2.f * p1.x - p2.x - p0.x, 2.f * p1.y - p2.y - p0.y);
    float2 u = make_float2(2.f * p1.x + p2.x + p0.x, 2.f * p1.y + p2.y + p0.y);

    float2 en, ep;
    if (n & 1) {
        en = make_float2(1.f, 0.f);
    } else {
        float s, c; sincosf(ph[n >> 1], &s, &c);
        en = make_float2(c, s);
    }
    int nm = (n - 1) & (NN - 1);
    if (nm & 1) {
        ep = make_float2(1.f, 0.f);
    } else {
        float s, c; sincosf(ph[nm >> 1], &s, &c);
        ep = make_float2(c, s);
    }

    float2 diag = cmul(en, v);
    diag.x *= 0.25f; diag.y *= 0.25f;

    float2 iu = make_float2(-u.y, u.x);         // i * u
    float2 off = cmul(ep, iu);
    off.x *= 0.25f; off.y *= 0.25f;

    g_DG[l * NN + n] = diag;
    g_OP[l * NN + (n ^ 1)] = off;               // partner-indexed for coalesced read
}

// ---------------- kernel 2: compose W = f(I) ----------------
// Each block propagates RB basis rows; thread i owns element i.
// Layer l: shift s (0 for l=0, +1 odd l, -1 even l>=1); couple pairs.
// x_new[i] = x_perm[i]*d[l,i] + x_perm[i^1]*off[l,i^1]; x_perm[i] = x[(i+s)&255].
#define RB 4
__global__ __launch_bounds__(NN) void build_w_kernel(const float* __restrict__ gamma) {
    __shared__ float2 bufA[RB][NN];
    __shared__ float2 bufB[RB][NN];

    int i = threadIdx.x;
    int r0 = blockIdx.x * RB;

    for (int r = 0; r < RB; r++) {
        int j = r0 + r;
        float2 v = make_float2(0.f, 0.f);
        if (i == j) {
            float s, c; sincosf(gamma[j], &s, &c);
            v = make_float2(c, s);                 // input phase screen e^{i*gamma_j}
        }
        bufA[r][i] = v;
    }
    __syncthreads();

    float2 (*A)[NN] = bufA;
    float2 (*Bx)[NN] = bufB;

    for (int l = 0; l < LL; l++) {
        int s = (l == 0) ? 0 : ((l & 1) ? 1 : -1);
        float2 d  = g_DG[l * NN + i];
        float2 op = g_OP[l * NN + i];
        int ia = (i + s) & (NN - 1);
        int ib = ((i ^ 1) + s) & (NN - 1);
#pragma unroll
        for (int r = 0; r < RB; r++) {
            float2 t = A[r][ia];
            float2 u = A[r][ib];
            float2 w;
            w.x = t.x * d.x - t.y * d.y + u.x * op.x - u.y * op.y;
            w.y = t.x * d.y + t.y * d.x + u.x * op.y + u.y * op.x;
            Bx[r][i] = w;
        }
        __syncthreads();
        float2 (*tmp)[NN] = A; A = Bx; Bx = tmp;
    }

    // final right-perm: x_new[i] = x[(i-1)&255]; store duplicated layout
    int src = (i - 1) & (NN - 1);
    for (int r = 0; r < RB; r++) {
        float2 w = A[r][src];
        g_WG[(r0 + r) * NN + i] = make_float4(w.x, w.y, -w.y, w.x);
    }
}

// ---------------- kernel 3: complex GEMM Y = X * W via fma.f32x2 ----------------
// Block tile: 128 batch rows x 128 complex cols, BK=8. 256 threads, 8x8 per thread.
// xs[kk][m] = (xr,xr,xi,xi); ws[kk][n] = (wr,wi,-wi,wr).
// acc(yr,yi) += (xr,xr)*(wr,wi); acc += (xi,xi)*(-wi,wr).
#define BM 128
#define BNC 128
#define BK 8

__global__ __launch_bounds__(256, 1) void gemm_kernel(const float* __restrict__ xre,
                                                      const float* __restrict__ xim,
                                                      float* __restrict__ out) {
    __shared__ float4 xs[BK][BM];
    __shared__ float4 ws[BK][BNC];

    int tid = threadIdx.x;
    int m0 = blockIdx.x * BM;
    int n0 = blockIdx.y * BNC;
    int tx = tid & 15;        // 16 col groups, cols n = tx + 16*j
    int ty = tid >> 4;        // 16 row groups, rows m = ty + 16*i

    unsigned long long acc[8][8];
#pragma unroll
    for (int a = 0; a < 8; a++)
#pragma unroll
        for (int b = 0; b < 8; b++) acc[a][b] = 0ull;

    // X-load mapping: thread -> (m = tid>>1, kk0 = (tid&1)*4)
    int xm = tid >> 1;
    int xk0 = (tid & 1) * 4;
    // W-load mapping: thread -> (kk = tid>>5, n = (tid&31) + 32*q)
    int wk = tid >> 5;
    int wn = tid & 31;

    for (int kc = 0; kc < NN; kc += BK) {
        {
            const float4 vr = *(const float4*)(xre + (m0 + xm) * NN + kc + xk0);
            const float4 vi = *(const float4*)(xim + (m0 + xm) * NN + kc + xk0);
            xs[xk0 + 0][xm] = make_float4(vr.x, vr.x, vi.x, vi.x);
            xs[xk0 + 1][xm] = make_float4(vr.y, vr.y, vi.y, vi.y);
            xs[xk0 + 2][xm] = make_float4(vr.z, vr.z, vi.z, vi.z);
            xs[xk0 + 3][xm] = make_float4(vr.w, vr.w, vi.w, vi.w);
        }
        {
            const float4* pw = g_WG + (kc + wk) * NN + n0;
#pragma unroll
            for (int q = 0; q < 4; q++)
                ws[wk][wn + 32 * q] = pw[wn + 32 * q];
        }
        __syncthreads();

#pragma unroll
        for (int kk = 0; kk < BK; kk++) {
            unsigned long long w1[8], w2[8];
#pragma unroll
            for (int j = 0; j < 8; j++) {
                ulonglong2 wv = *(const ulonglong2*)&ws[kk][tx + 16 * j];
                w1[j] = wv.x;   // (wr, wi)
                w2[j] = wv.y;   // (-wi, wr)
            }
#pragma unroll
            for (int im = 0; im < 8; im++) {
                ulonglong2 xv = *(const ulonglong2*)&xs[kk][ty + 16 * im];
                unsigned long long a1 = xv.x;   // (xr, xr)
                unsigned long long a2 = xv.y;   // (xi, xi)
#pragma unroll
                for (int j = 0; j < 8; j++) {
                    FMA_F32X2(acc[im][j], a1, w1[j]);
                    FMA_F32X2(acc[im][j], a2, w2[j]);
                }
            }
        }
        __syncthreads();
    }

    // write (2, B, N): re plane then im plane
    float* outr = out;
    float* outi = out + (size_t)BB * NN;
#pragma unroll
    for (int im = 0; im < 8; im++) {
        int m = m0 + ty + 16 * im;
#pragma unroll
        for (int j = 0; j < 8; j++) {
            int n = n0 + tx + 16 * j;
            union { unsigned long long u; float2 f; } cv;
            cv.u = acc[im][j];
            outr[m * NN + n] = cv.f.x;
            outi[m * NN + n] = cv.f.y;
        }
    }
}

// ---------------- launch ----------------
extern "C" void kernel_launch(void* const* d_in, const int* in_sizes, int n_in,
                              void* d_out, int out_size) {
    const float* x_re  = (const float*)d_in[0];
    const float* x_im  = (const float*)d_in[1];
    const float* theta = (const float*)d_in[2];
    const float* phi   = (const float*)d_in[3];
    const float* gamma = (const float*)d_in[4];
    // d_in[5] perm_idx, d_in[6] pairwise_perm_idx: fixed by construction, derived analytically
    float* out = (float*)d_out;

    coeff_kernel<<<LL, NN>>>(theta, phi);
    build_w_kernel<<<NN / RB, NN>>>(gamma);
    dim3 grid(BB / BM, NN / BNC);
    gemm_kernel<<<grid, 256>>>(x_re, x_im, out);
}

// round 3
// speedup vs baseline: 2.1194x; 2.1194x over previous
#include <cuda_runtime.h>
#include <cuda_bf16.h>
#include <cstdint>

#define NN 256
#define LL 256
#define BB 16384

#if defined(__CUDA_ARCH_FEAT_SM103_ALL) || defined(__CUDA_ARCH_FEAT_SM100_ALL) || defined(__CUDA_ARCH_FEAT_SM101_ALL)
#define HAS_TC 1
#else
#define HAS_TC 0
#endif

// ---------------- scratch ----------------
__device__ float2 g_DG[LL * NN];
__device__ float2 g_OP[LL * NN];
__device__ __nv_bfloat16 g_Bh[512 * 512];   // B[n][k] = W'^T, hi part
__device__ __nv_bfloat16 g_Bl[512 * 512];   // lo part
__device__ float4 g_WG4[NN * NN];           // fallback layout: (wr, wi, -wi, wr)
__device__ int g_has_tc = 0;                // set by tcgen05 kernel when its body runs

// ---------------- common helpers ----------------
__device__ __forceinline__ uint32_t smem_u32(const void* p) {
    uint32_t a;
    asm("{ .reg .u64 t; cvta.to.shared.u64 t, %1; cvt.u32.u64 %0, t; }" : "=r"(a) : "l"(p));
    return a;
}
__device__ __forceinline__ float2 cmul(float2 a, float2 b) {
    return make_float2(a.x * b.x - a.y * b.y, a.x * b.y + a.y * b.x);
}
union BU { __nv_bfloat162 h; uint32_t u; };

#define FMA_F32X2(d, a, b) \
    asm("fma.rn.f32x2 %0, %1, %2, %0;" : "+l"(d) : "l"(a), "l"(b))

// ---------------- tcgen05 helpers (sm_103a-only pass) ----------------
#define TCGEN05_ALLOC(sa, n) \
    asm volatile("tcgen05.alloc.cta_group::1.sync.aligned.shared::cta.b32 [%0], %1;" :: "r"((uint32_t)(sa)), "r"((uint32_t)(n)) : "memory")
#define TCGEN05_DEALLOC(t, n) \
    asm volatile("tcgen05.dealloc.cta_group::1.sync.aligned.b32 %0, %1;" :: "r"(t), "r"((uint32_t)(n)))
#define TCGEN05_RELINQ() \
    asm volatile("tcgen05.relinquish_alloc_permit.cta_group::1.sync.aligned;")
#define TCGEN05_COMMIT(mb) \
    asm volatile("tcgen05.commit.cta_group::1.mbarrier::arrive::one.shared::cluster.b64 [%0];" :: "r"((uint32_t)(mb)) : "memory")
#define TCGEN05_WAIT_LD() asm volatile("tcgen05.wait::ld.sync.aligned;" ::: "memory")
#define TCGEN05_FENCE_AFTER() asm volatile("tcgen05.fence::after_thread_sync;" ::: "memory")
#define FENCE_ASYNC_SHARED() asm volatile("fence.proxy.async.shared::cta;" ::: "memory")

#define MBARRIER_INIT(mb, cnt) \
    asm volatile("mbarrier.init.shared.b64 [%0], %1;" :: "r"((uint32_t)(mb)), "r"((uint32_t)(cnt)) : "memory")
#define MBARRIER_ARRIVE(mb) \
    asm volatile("mbarrier.arrive.shared.b64 _, [%0];" :: "r"((uint32_t)(mb)) : "memory")
#define MBARRIER_WAIT_PARITY(mb, ph) do { \
    uint32_t _mb = (uint32_t)(mb), _ph = (uint32_t)(ph), _done; \
    asm volatile("{\n\t.reg .pred p;\n\tmbarrier.try_wait.parity.acquire.cta.shared::cta.b64 p, [%1], %2;\n\tselp.b32 %0, 1, 0, p;\n\t}" \
        : "=r"(_done) : "r"(_mb), "r"(_ph) : "memory"); \
    if (!_done) { \
        asm volatile("{\n\t.reg .pred P1;\n\tWL_%=:\n\tmbarrier.try_wait.parity.acquire.cta.shared::cta.b64 P1, [%0], %1, 0x989680;\n\t@P1 bra.uni WD_%=;\n\tbra.uni WL_%=;\n\tWD_%=:\n\t}" \
            :: "r"(_mb), "r"(_ph) : "memory"); \
    } } while (0)

#define STS128(addr, v0, v1, v2, v3) \
    asm volatile("st.shared.v4.b32 [%0], {%1,%2,%3,%4};" :: "r"(addr), "r"(v0), "r"(v1), "r"(v2), "r"(v3) : "memory")

#define TCGEN05_LD_32X32B_X32(r, ta) \
    asm volatile("tcgen05.ld.sync.aligned.32x32b.x32.b32 " \
        "{%0,%1,%2,%3,%4,%5,%6,%7,%8,%9,%10,%11,%12,%13,%14,%15," \
        "%16,%17,%18,%19,%20,%21,%22,%23,%24,%25,%26,%27,%28,%29,%30,%31}, [%32];" \
        : "=r"((r)[0]), "=r"((r)[1]), "=r"((r)[2]), "=r"((r)[3]), "=r"((r)[4]), "=r"((r)[5]), "=r"((r)[6]), "=r"((r)[7]), \
          "=r"((r)[8]), "=r"((r)[9]), "=r"((r)[10]), "=r"((r)[11]), "=r"((r)[12]), "=r"((r)[13]), "=r"((r)[14]), "=r"((r)[15]), \
          "=r"((r)[16]), "=r"((r)[17]), "=r"((r)[18]), "=r"((r)[19]), "=r"((r)[20]), "=r"((r)[21]), "=r"((r)[22]), "=r"((r)[23]), \
          "=r"((r)[24]), "=r"((r)[25]), "=r"((r)[26]), "=r"((r)[27]), "=r"((r)[28]), "=r"((r)[29]), "=r"((r)[30]), "=r"((r)[31]) \
        : "r"(ta))

#define SWZ64(o) ((o) ^ (((o) >> 3) & 0x30))

#if HAS_TC
__device__ __forceinline__ uint32_t elect_one_pred() {
    uint32_t p;
    asm volatile("{\n\t.reg .pred p;\n\telect.sync _|p, 0xFFFFFFFF;\n\tselp.b32 %0, 1, 0, p;\n\t}" : "=r"(p));
    return p;
}
// SW64 K-major descriptor: layout=4, version=1, SBO=32 (512B per 8-row group), LBO=1 (16B)
__device__ __forceinline__ uint64_t make_desc_sw64(uint32_t base) {
    return ((uint64_t)4 << 61) | ((uint64_t)1 << 46) | ((uint64_t)32 << 32) | ((uint64_t)1 << 16)
         | (uint64_t)((base >> 4) & 0x3FFF);
}
__device__ __forceinline__ void mma_f16_ss_cg1(uint32_t d, uint64_t ad, uint64_t bd,
                                               uint32_t idesc, uint32_t en) {
    asm volatile(
        "{\n\t.reg .pred p;\n\tsetp.ne.u32 p, %5, 0;\n\t"
        "tcgen05.mma.cta_group::1.kind::f16 [%0], %1, %2, %3, {%4,%4,%4,%4}, p;\n\t}"
        :: "r"(d), "l"(ad), "l"(bd), "r"(idesc), "r"(0u), "r"(en) : "memory");
}
#endif

// ---------------- kernel 1: per-layer MZI coefficients ----------------
__global__ void coeff_kernel(const float* __restrict__ theta,
                             const float* __restrict__ phi) {
    int l = blockIdx.x;
    int n = threadIdx.x;
    const float* th = theta + l * (NN / 2);
    const float* ph = phi + l * (NN / 2);

    auto ipsl = [&](int k) -> float2 {
        k &= (NN - 1);
        float ang = 0.5f * th[k >> 1];
        if (k & 1) ang = -ang;
        float s, c; sincosf(ang, &s, &c);
        return make_float2(c, s);
    };
    float2 p0 = ipsl(n - 1), p1 = ipsl(n), p2 = ipsl(n + 1);
    float2 v = make_float2(2.f * p1.x - p2.x - p0.x, 2.f * p1.y - p2.y - p0.y);
    float2 u = make_float2(2.f * p1.x + p2.x + p0.x, 2.f * p1.y + p2.y + p0.y);

    float2 en, ep;
    if (n & 1) en = make_float2(1.f, 0.f);
    else { float s, c; sincosf(ph[n >> 1], &s, &c); en = make_float2(c, s); }
    int nm = (n - 1) & (NN - 1);
    if (nm & 1) ep = make_float2(1.f, 0.f);
    else { float s, c; sincosf(ph[nm >> 1], &s, &c); ep = make_float2(c, s); }

    float2 diag = cmul(en, v); diag.x *= 0.25f; diag.y *= 0.25f;
    float2 iu = make_float2(-u.y, u.x);
    float2 off = cmul(ep, iu); off.x *= 0.25f; off.y *= 0.25f;

    g_DG[l * NN + n] = diag;
    g_OP[l * NN + (n ^ 1)] = off;
}

// ---------------- kernel 2: compose W, emit both layouts ----------------
#define RB 4
__global__ __launch_bounds__(NN) void build_w_kernel(const float* __restrict__ gamma) {
    __shared__ float2 bufA[RB][NN];
    __shared__ float2 bufB[RB][NN];
    int i = threadIdx.x;
    int r0 = blockIdx.x * RB;

    for (int r = 0; r < RB; r++) {
        int j = r0 + r;
        float2 v = make_float2(0.f, 0.f);
        if (i == j) { float s, c; sincosf(gamma[j], &s, &c); v = make_float2(c, s); }
        bufA[r][i] = v;
    }
    __syncthreads();

    float2 (*A)[NN] = bufA;
    float2 (*Bx)[NN] = bufB;
    for (int l = 0; l < LL; l++) {
        int s = (l == 0) ? 0 : ((l & 1) ? 1 : -1);
        float2 d  = g_DG[l * NN + i];
        float2 op = g_OP[l * NN + i];
        int ia = (i + s) & (NN - 1);
        int ib = ((i ^ 1) + s) & (NN - 1);
#pragma unroll
        for (int r = 0; r < RB; r++) {
            float2 t = A[r][ia];
            float2 u = A[r][ib];
            float2 w;
            w.x = t.x * d.x - t.y * d.y + u.x * op.x - u.y * op.y;
            w.y = t.x * d.y + t.y * d.x + u.x * op.y + u.y * op.x;
            Bx[r][i] = w;
        }
        __syncthreads();
        float2 (*tmp)[NN] = A; A = Bx; Bx = tmp;
    }

    int src = (i - 1) & (NN - 1);
    for (int r = 0; r < RB; r++) {
        float2 w = A[r][src];        // W[k][n], k = r0+r, n = i
        int k = r0 + r, n = i;
        __nv_bfloat16 hr = __float2bfloat16(w.x);
        __nv_bfloat16 lr = __float2bfloat16(w.x - __bfloat162float(hr));
        __nv_bfloat16 hi = __float2bfloat16(w.y);
        __nv_bfloat16 li = __float2bfloat16(w.y - __bfloat162float(hi));
        __nv_bfloat16 nhi = __hneg(hi), nli = __hneg(li);
        // B[n][k]=Wr, B[n][256+k]=-Wi, B[256+n][k]=Wi, B[256+n][256+k]=Wr
        g_Bh[n * 512 + k] = hr;               g_Bl[n * 512 + k] = lr;
        g_Bh[n * 512 + 256 + k] = nhi;        g_Bl[n * 512 + 256 + k] = nli;
        g_Bh[(256 + n) * 512 + k] = hi;       g_Bl[(256 + n) * 512 + k] = li;
        g_Bh[(256 + n) * 512 + 256 + k] = hr; g_Bl[(256 + n) * 512 + 256 + k] = lr;
        g_WG4[k * NN + n] = make_float4(w.x, w.y, -w.y, w.x);
    }
}

// ---------------- kernel 3a: tcgen05 bf16-split GEMM (sm_103a only) ----------------
#define KC 32
#define SMEM_TMEM 0
#define MB_FULL(s)  (16 + (s) * 8)
#define MB_EMPTY(s) (32 + (s) * 8)
#define MB_DONE     48
#define STAGE_SZ    81920
#define STAGE_BASE(s) (1024 + (s) * STAGE_SZ)
#define A_HI_OFF 0
#define A_LO_OFF 8192
#define B_HI_OFF 16384
#define B_LO_OFF 49152
#define SMEM_TOTAL (1024 + 2 * STAGE_SZ)

__global__ __launch_bounds__(256, 1)
void gemm_tc_kernel(const float* __restrict__ xre, const float* __restrict__ xim,
                    float* __restrict__ out) {
#if HAS_TC
    extern __shared__ char smem[];
    const uint32_t sb = smem_u32(smem);
    int tid = threadIdx.x, wid = tid >> 5, lane = tid & 31;
    int m0 = blockIdx.x * 128;

    if (tid == 0) g_has_tc = 1;   // mark: tensor-core image is live

    if (wid == 4) TCGEN05_ALLOC(sb + SMEM_TMEM, 512);
    if (tid == 0) {
        MBARRIER_INIT(sb + MB_FULL(0), 7);
        MBARRIER_INIT(sb + MB_FULL(1), 7);
        MBARRIER_INIT(sb + MB_EMPTY(0), 1);
        MBARRIER_INIT(sb + MB_EMPTY(1), 1);
        MBARRIER_INIT(sb + MB_DONE, 1);
    }
    __syncthreads();
    uint32_t tmem;
    asm volatile("ld.shared.b32 %0, [%1];" : "=r"(tmem) : "r"(sb + SMEM_TMEM));

    if (wid < 4) {
        // ---- A producer: thread = batch row m; LDG fp32 -> bf16 hi/lo -> STS (SW64)
        int m = tid;
        const float* rowre = xre + (size_t)(m0 + m) * NN;
        const float* rowim = xim + (size_t)(m0 + m) * NN;
        for (int it = 0; it < 16; ++it) {
            int s = it & 1;
            if (it >= 2) MBARRIER_WAIT_PARITY(sb + MB_EMPTY(s), ((it >> 1) - 1) & 1);
            const float* src = (it < 8) ? rowre + it * KC : rowim + (it - 8) * KC;
            uint32_t ahi = sb + STAGE_BASE(s) + A_HI_OFF;
            uint32_t alo = sb + STAGE_BASE(s) + A_LO_OFF;
#pragma unroll
            for (int g = 0; g < 4; ++g) {
                float4 a = ((const float4*)src)[2 * g];
                float4 b = ((const float4*)src)[2 * g + 1];
                BU h0, h1, h2, h3, l0, l1, l2, l3;
                h0.h = __floats2bfloat162_rn(a.x, a.y);
                h1.h = __floats2bfloat162_rn(a.z, a.w);
                h2.h = __floats2bfloat162_rn(b.x, b.y);
                h3.h = __floats2bfloat162_rn(b.z, b.w);
                float2 f0 = __bfloat1622float2(h0.h), f1 = __bfloat1622float2(h1.h);
                float2 f2 = __bfloat1622float2(h2.h), f3 = __bfloat1622float2(h3.h);
                l0.h = __floats2bfloat162_rn(a.x - f0.x, a.y - f0.y);
                l1.h = __floats2bfloat162_rn(a.z - f1.x, a.w - f1.y);
                l2.h = __floats2bfloat162_rn(b.x - f2.x, b.y - f2.y);
                l3.h = __floats2bfloat162_rn(b.z - f3.x, b.w - f3.y);
                uint32_t off = SWZ64((uint32_t)(m * 64 + g * 16));
                STS128(ahi + off, h0.u, h1.u, h2.u, h3.u);
                STS128(alo + off, l0.u, l1.u, l2.u, l3.u);
            }
            FENCE_ASYNC_SHARED();
            __syncwarp();
            if (lane == 0) MBARRIER_ARRIVE(sb + MB_FULL(s));
        }
    } else if (wid >= 5) {
        // ---- B producer: warps 5-7 cp.async g_Bh/g_Bl chunks (SW64)
        int tb = (wid - 5) * 32 + lane;  // 0..95
        const char* srch = (const char*)g_Bh;
        const char* srcl = (const char*)g_Bl;
        for (int it = 0; it < 16; ++it) {
            int s = it & 1;
            if (it >= 2) MBARRIER_WAIT_PARITY(sb + MB_EMPTY(s), ((it >> 1) - 1) & 1);
            int kb = it * (KC * 2);  // byte offset of this k-chunk within a 1024B row
            uint32_t bbase = sb + STAGE_BASE(s);
            for (int g = tb; g < 4096; g += 96) {
                int buf = g >> 11;
                int gg = g & 2047;
                int n = gg >> 2, gc = gg & 3;
                const char* src = (buf ? srcl : srch) + n * 1024 + kb + gc * 16;
                uint32_t dst = bbase + (buf ? B_LO_OFF : B_HI_OFF) + SWZ64((uint32_t)(n * 64 + gc * 16));
                asm volatile("cp.async.cg.shared.global [%0], [%1], 16;" :: "r"(dst), "l"(src) : "memory");
            }
            asm volatile("cp.async.commit_group;" ::: "memory");
            asm volatile("cp.async.wait_group 0;" ::: "memory");
            FENCE_ASYNC_SHARED();
            __syncwarp();
            if (lane == 0) MBARRIER_ARRIVE(sb + MB_FULL(s));
        }
    } else {
        // ---- MMA warp (wid == 4)
        const uint32_t IDESC = (1u << 4) | (1u << 7) | (1u << 10) | (32u << 17) | (8u << 24);
        for (int it = 0; it < 16; ++it) {
            int s = it & 1;
            MBARRIER_WAIT_PARITY(sb + MB_FULL(s), (it >> 1) & 1);
            if (elect_one_pred()) {
                uint32_t stage = sb + STAGE_BASE(s);
                uint64_t ah = make_desc_sw64(stage + A_HI_OFF);
                uint64_t al = make_desc_sw64(stage + A_LO_OFF);
                uint64_t bh = make_desc_sw64(stage + B_HI_OFF);
                uint64_t bl = make_desc_sw64(stage + B_LO_OFF);
#pragma unroll
                for (int seg = 0; seg < 3; ++seg) {
                    uint64_t ad = (seg == 2) ? al : ah;
                    uint64_t bd = (seg == 1) ? bl : bh;
#pragma unroll
                    for (int kk = 0; kk < 2; ++kk) {
#pragma unroll
                        for (int nh = 0; nh < 2; ++nh) {
                            uint32_t en = !(it == 0 && seg == 0 && kk == 0);
                            mma_f16_ss_cg1(tmem + nh * 256, ad + kk * 2,
                                           bd + (uint64_t)nh * 1024 + kk * 2, IDESC, en);
                        }
                    }
                }
                TCGEN05_COMMIT((it == 15) ? (sb + MB_DONE) : (sb + MB_EMPTY(s)));
            }
        }
    }

    // ---- epilogue: WG0 -> re plane (cols 0-255), WG1 -> im plane (cols 256-511)
    MBARRIER_WAIT_PARITY(sb + MB_DONE, 0);
    TCGEN05_FENCE_AFTER();
    {
        int wg = tid >> 7;
        int wt = tid & 127;
        int m = m0 + wt;
        float* dst = out + (size_t)wg * BB * NN + (size_t)m * NN;
        uint32_t colbase = tmem + wg * 256;
#pragma unroll
        for (int c = 0; c < 8; ++c) {
            uint32_t r[32];
            TCGEN05_LD_32X32B_X32(r, colbase + c * 32);
            TCGEN05_WAIT_LD();
            float4* d4 = (float4*)(dst + c * 32);
#pragma unroll
            for (int q = 0; q < 8; ++q)
                d4[q] = make_float4(__uint_as_float(r[4 * q]), __uint_as_float(r[4 * q + 1]),
                                    __uint_as_float(r[4 * q + 2]), __uint_as_float(r[4 * q + 3]));
        }
    }
    __syncthreads();
    if (wid == 4) {
        TCGEN05_RELINQ();
        TCGEN05_DEALLOC(tmem, 512);
    }
#endif  // HAS_TC
}

// ---------------- kernel 3b: fallback f32x2 GEMM (proven in R1) ----------------
#define BM 128
#define BNC 128
#define BK 8

__global__ __launch_bounds__(256, 1) void gemm_fb_kernel(const float* __restrict__ xre,
                                                         const float* __restrict__ xim,
                                                         float* __restrict__ out) {
    if (g_has_tc) return;   // tensor-core kernel already produced the output

    __shared__ float4 xs[BK][BM];
    __shared__ float4 ws[BK][BNC];

    int tid = threadIdx.x;
    int m0 = blockIdx.x * BM;
    int n0 = blockIdx.y * BNC;
    int tx = tid & 15;
    int ty = tid >> 4;

    unsigned long long acc[8][8];
#pragma unroll
    for (int a = 0; a < 8; a++)
#pragma unroll
        for (int b = 0; b < 8; b++) acc[a][b] = 0ull;

    int xm = tid >> 1;
    int xk0 = (tid & 1) * 4;
    int wk = tid >> 5;
    int wn = tid & 31;

    for (int kc = 0; kc < NN; kc += BK) {
        {
            const float4 vr = *(const float4*)(xre + (m0 + xm) * NN + kc + xk0);
            const float4 vi = *(const float4*)(xim + (m0 + xm) * NN + kc + xk0);
            xs[xk0 + 0][xm] = make_float4(vr.x, vr.x, vi.x, vi.x);
            xs[xk0 + 1][xm] = make_float4(vr.y, vr.y, vi.y, vi.y);
            xs[xk0 + 2][xm] = make_float4(vr.z, vr.z, vi.z, vi.z);
            xs[xk0 + 3][xm] = make_float4(vr.w, vr.w, vi.w, vi.w);
        }
        {
            const float4* pw = g_WG4 + (kc + wk) * NN + n0;
#pragma unroll
            for (int q = 0; q < 4; q++)
                ws[wk][wn + 32 * q] = pw[wn + 32 * q];
        }
        __syncthreads();

#pragma unroll
        for (int kk = 0; kk < BK; kk++) {
            unsigned long long w1[8], w2[8];
#pragma unroll
            for (int j = 0; j < 8; j++) {
                ulonglong2 wv = *(const ulonglong2*)&ws[kk][tx + 16 * j];
                w1[j] = wv.x;
                w2[j] = wv.y;
            }
#pragma unroll
            for (int im = 0; im < 8; im++) {
                ulonglong2 xv = *(const ulonglong2*)&xs[kk][ty + 16 * im];
                unsigned long long a1 = xv.x;
                unsigned long long a2 = xv.y;
#pragma unroll
                for (int j = 0; j < 8; j++) {
                    FMA_F32X2(acc[im][j], a1, w1[j]);
                    FMA_F32X2(acc[im][j], a2, w2[j]);
                }
            }
        }
        __syncthreads();
    }

    float* outr = out;
    float* outi = out + (size_t)BB * NN;
#pragma unroll
    for (int im = 0; im < 8; im++) {
        int m = m0 + ty + 16 * im;
#pragma unroll
        for (int j = 0; j < 8; j++) {
            int n = n0 + tx + 16 * j;
            union { unsigned long long u; float2 f; } cv;
            cv.u = acc[im][j];
            outr[m * NN + n] = cv.f.x;
            outi[m * NN + n] = cv.f.y;
        }
    }
}

// ---------------- launch ----------------
extern "C" void kernel_launch(void* const* d_in, const int* in_sizes, int n_in,
                              void* d_out, int out_size) {
    const float* x_re  = (const float*)d_in[0];
    const float* x_im  = (const float*)d_in[1];
    const float* theta = (const float*)d_in[2];
    const float* phi   = (const float*)d_in[3];
    const float* gamma = (const float*)d_in[4];
    float* out = (float*)d_out;

    cudaFuncSetAttribute(gemm_tc_kernel, cudaFuncAttributeMaxDynamicSharedMemorySize, SMEM_TOTAL);

    coeff_kernel<<<LL, NN>>>(theta, phi);
    build_w_kernel<<<NN / RB, NN>>>(gamma);
    gemm_tc_kernel<<<BB / 128, 256, SMEM_TOTAL>>>(x_re, x_im, out);
    dim3 grid_fb(BB / BM, NN / BNC);
    gemm_fb_kernel<<<grid_fb, 256>>>(x_re, x_im, out);
}

// round 4
// speedup vs baseline: 3.4597x; 1.6324x over previous
#include <cuda_runtime.h>
#include <cuda_bf16.h>
#include <cstdint>

#define NN 256
#define LL 256
#define BB 16384

#if defined(__CUDA_ARCH_FEAT_SM103_ALL) || defined(__CUDA_ARCH_FEAT_SM100_ALL) || defined(__CUDA_ARCH_FEAT_SM101_ALL)
#define HAS_TC 1
#else
#define HAS_TC 0
#endif

typedef unsigned long long u64;

// ---------------- scratch ----------------
__device__ float2 g_DG[LL * NN];
__device__ float2 g_OP[LL * NN];
__device__ __nv_bfloat16 g_Bh[512 * 512];   // B[n][k] = W'^T, hi part
__device__ __nv_bfloat16 g_Bl[512 * 512];   // lo part

// ---------------- common helpers ----------------
__device__ __forceinline__ uint32_t smem_u32(const void* p) {
    uint32_t a;
    asm("{ .reg .u64 t; cvta.to.shared.u64 t, %1; cvt.u32.u64 %0, t; }" : "=r"(a) : "l"(p));
    return a;
}
__device__ __forceinline__ float2 cmul(float2 a, float2 b) {
    return make_float2(a.x * b.x - a.y * b.y, a.x * b.y + a.y * b.x);
}
union BU { __nv_bfloat162 h; uint32_t u; };
union F2U { float2 f; u64 u; };

#define FMA_F32X2(d, a, b) \
    asm("fma.rn.f32x2 %0, %1, %2, %0;" : "+l"(d) : "l"(a), "l"(b))
#define MUL_F32X2(d, a, b) \
    asm("mul.rn.f32x2 %0, %1, %2;" : "=l"(d) : "l"(a), "l"(b))
__device__ __forceinline__ u64 pack2(float lo, float hi) {
    u64 r; asm("mov.b64 %0, {%1,%2};" : "=l"(r) : "f"(lo), "f"(hi)); return r;
}
__device__ __forceinline__ u64 dup2(float x) {
    u64 r; asm("mov.b64 %0, {%1,%1};" : "=l"(r) : "f"(x)); return r;
}

// ---------------- tcgen05 helpers ----------------
#define TCGEN05_ALLOC(sa, n) \
    asm volatile("tcgen05.alloc.cta_group::1.sync.aligned.shared::cta.b32 [%0], %1;" :: "r"((uint32_t)(sa)), "r"((uint32_t)(n)) : "memory")
#define TCGEN05_DEALLOC(t, n) \
    asm volatile("tcgen05.dealloc.cta_group::1.sync.aligned.b32 %0, %1;" :: "r"(t), "r"((uint32_t)(n)))
#define TCGEN05_RELINQ() \
    asm volatile("tcgen05.relinquish_alloc_permit.cta_group::1.sync.aligned;")
#define TCGEN05_COMMIT(mb) \
    asm volatile("tcgen05.commit.cta_group::1.mbarrier::arrive::one.shared::cluster.b64 [%0];" :: "r"((uint32_t)(mb)) : "memory")
#define TCGEN05_WAIT_LD() asm volatile("tcgen05.wait::ld.sync.aligned;" ::: "memory")
#define TCGEN05_FENCE_AFTER() asm volatile("tcgen05.fence::after_thread_sync;" ::: "memory")
#define FENCE_ASYNC_SHARED() asm volatile("fence.proxy.async.shared::cta;" ::: "memory")

#define MBARRIER_INIT(mb, cnt) \
    asm volatile("mbarrier.init.shared.b64 [%0], %1;" :: "r"((uint32_t)(mb)), "r"((uint32_t)(cnt)) : "memory")
#define MBARRIER_ARRIVE(mb) \
    asm volatile("mbarrier.arrive.shared.b64 _, [%0];" :: "r"((uint32_t)(mb)) : "memory")
#define MBARRIER_WAIT_PARITY(mb, ph) do { \
    uint32_t _mb = (uint32_t)(mb), _ph = (uint32_t)(ph), _done; \
    asm volatile("{\n\t.reg .pred p;\n\tmbarrier.try_wait.parity.acquire.cta.shared::cta.b64 p, [%1], %2;\n\tselp.b32 %0, 1, 0, p;\n\t}" \
        : "=r"(_done) : "r"(_mb), "r"(_ph) : "memory"); \
    if (!_done) { \
        asm volatile("{\n\t.reg .pred P1;\n\tWL_%=:\n\tmbarrier.try_wait.parity.acquire.cta.shared::cta.b64 P1, [%0], %1, 0x989680;\n\t@P1 bra.uni WD_%=;\n\tbra.uni WL_%=;\n\tWD_%=:\n\t}" \
            :: "r"(_mb), "r"(_ph) : "memory"); \
    } } while (0)

#define TCGEN05_LD_32X32B_X32(r, ta) \
    asm volatile("tcgen05.ld.sync.aligned.32x32b.x32.b32 " \
        "{%0,%1,%2,%3,%4,%5,%6,%7,%8,%9,%10,%11,%12,%13,%14,%15," \
        "%16,%17,%18,%19,%20,%21,%22,%23,%24,%25,%26,%27,%28,%29,%30,%31}, [%32];" \
        : "=r"((r)[0]), "=r"((r)[1]), "=r"((r)[2]), "=r"((r)[3]), "=r"((r)[4]), "=r"((r)[5]), "=r"((r)[6]), "=r"((r)[7]), \
          "=r"((r)[8]), "=r"((r)[9]), "=r"((r)[10]), "=r"((r)[11]), "=r"((r)[12]), "=r"((r)[13]), "=r"((r)[14]), "=r"((r)[15]), \
          "=r"((r)[16]), "=r"((r)[17]), "=r"((r)[18]), "=r"((r)[19]), "=r"((r)[20]), "=r"((r)[21]), "=r"((r)[22]), "=r"((r)[23]), \
          "=r"((r)[24]), "=r"((r)[25]), "=r"((r)[26]), "=r"((r)[27]), "=r"((r)[28]), "=r"((r)[29]), "=r"((r)[30]), "=r"((r)[31]) \
        : "r"(ta))

#define SWZ64(o) ((o) ^ (((o) >> 3) & 0x30))

#if HAS_TC
__device__ __forceinline__ uint32_t elect_one_pred() {
    uint32_t p;
    asm volatile("{\n\t.reg .pred p;\n\telect.sync _|p, 0xFFFFFFFF;\n\tselp.b32 %0, 1, 0, p;\n\t}" : "=r"(p));
    return p;
}
// SW64 K-major descriptor: layout=4, version=1, SBO=32 (512B per 8-row group), LBO=1 (16B)
__device__ __forceinline__ uint64_t make_desc_sw64(uint32_t base) {
    return ((uint64_t)4 << 61) | ((uint64_t)1 << 46) | ((uint64_t)32 << 32) | ((uint64_t)1 << 16)
         | (uint64_t)((base >> 4) & 0x3FFF);
}
__device__ __forceinline__ void mma_f16_ss_cg1(uint32_t d, uint64_t ad, uint64_t bd,
                                               uint32_t idesc, uint32_t en) {
    asm volatile(
        "{\n\t.reg .pred p;\n\tsetp.ne.u32 p, %5, 0;\n\t"
        "tcgen05.mma.cta_group::1.kind::f16 [%0], %1, %2, %3, {%4,%4,%4,%4}, p;\n\t}"
        :: "r"(d), "l"(ad), "l"(bd), "r"(idesc), "r"(0u), "r"(en) : "memory");
}
#endif

// ---------------- kernel 1: per-layer MZI coefficients ----------------
__global__ void coeff_kernel(const float* __restrict__ theta,
                             const float* __restrict__ phi) {
    int l = blockIdx.x;
    int n = threadIdx.x;
    const float* th = theta + l * (NN / 2);
    const float* ph = phi + l * (NN / 2);

    auto ipsl = [&](int k) -> float2 {
        k &= (NN - 1);
        float ang = 0.5f * th[k >> 1];
        if (k & 1) ang = -ang;
        float s, c; sincosf(ang, &s, &c);
        return make_float2(c, s);
    };
    float2 p0 = ipsl(n - 1), p1 = ipsl(n), p2 = ipsl(n + 1);
    float2 v = make_float2(2.f * p1.x - p2.x - p0.x, 2.f * p1.y - p2.y - p0.y);
    float2 u = make_float2(2.f * p1.x + p2.x + p0.x, 2.f * p1.y + p2.y + p0.y);

    float2 en, ep;
    if (n & 1) en = make_float2(1.f, 0.f);
    else { float s, c; sincosf(ph[n >> 1], &s, &c); en = make_float2(c, s); }
    int nm = (n - 1) & (NN - 1);
    if (nm & 1) ep = make_float2(1.f, 0.f);
    else { float s, c; sincosf(ph[nm >> 1], &s, &c); ep = make_float2(c, s); }

    float2 diag = cmul(en, v); diag.x *= 0.25f; diag.y *= 0.25f;
    float2 iu = make_float2(-u.y, u.x);
    float2 off = cmul(ep, iu); off.x *= 0.25f; off.y *= 0.25f;

    g_DG[l * NN + n] = diag;
    g_OP[l * NN + (n ^ 1)] = off;
}

// ---------------- kernel 2: compose W (prefetched coeffs, f32x2 math) ----------------
#define RB 2
__global__ __launch_bounds__(NN) void build_w_kernel(const float* __restrict__ gamma) {
    __shared__ float2 bufA[RB][NN];
    __shared__ float2 bufB[RB][NN];
    int i = threadIdx.x;
    int r0 = blockIdx.x * RB;

#pragma unroll
    for (int r = 0; r < RB; r++) {
        int j = r0 + r;
        float2 v = make_float2(0.f, 0.f);
        if (i == j) { float s, c; sincosf(gamma[j], &s, &c); v = make_float2(c, s); }
        bufA[r][i] = v;
    }

    float2 dnx = g_DG[i];     // prefetch layer 0
    float2 onx = g_OP[i];
    __syncthreads();

    float2 (*A)[NN] = bufA;
    float2 (*Bx)[NN] = bufB;
    for (int l = 0; l < LL; l++) {
        float2 d = dnx, o = onx;
        if (l + 1 < LL) {                 // prefetch next layer before compute/barrier
            dnx = g_DG[(l + 1) * NN + i];
            onx = g_OP[(l + 1) * NN + i];
        }
        int s = (l == 0) ? 0 : ((l & 1) ? 1 : -1);
        int ia = (i + s) & (NN - 1);
        int ib = ((i ^ 1) + s) & (NN - 1);

        u64 d1 = pack2(d.x, d.y), d2 = pack2(-d.y, d.x);
        u64 o1 = pack2(o.x, o.y), o2 = pack2(-o.y, o.x);
#pragma unroll
        for (int r = 0; r < RB; r++) {
            float2 t = A[r][ia];
            float2 u = A[r][ib];
            u64 w;
            MUL_F32X2(w, dup2(t.x), d1);
            FMA_F32X2(w, dup2(t.y), d2);
            FMA_F32X2(w, dup2(u.x), o1);
            FMA_F32X2(w, dup2(u.y), o2);
            F2U cv; cv.u = w;
            Bx[r][i] = cv.f;
        }
        __syncthreads();
        float2 (*tmp)[NN] = A; A = Bx; Bx = tmp;
    }

    int src = (i - 1) & (NN - 1);
#pragma unroll
    for (int r = 0; r < RB; r++) {
        float2 w = A[r][src];        // W[k][n], k = r0+r, n = i
        int k = r0 + r, n = i;
        __nv_bfloat16 hr = __float2bfloat16(w.x);
        __nv_bfloat16 lr = __float2bfloat16(w.x - __bfloat162float(hr));
        __nv_bfloat16 hi = __float2bfloat16(w.y);
        __nv_bfloat16 li = __float2bfloat16(w.y - __bfloat162float(hi));
        __nv_bfloat16 nhi = __hneg(hi), nli = __hneg(li);
        // B[n][k]=Wr, B[n][256+k]=-Wi, B[256+n][k]=Wi, B[256+n][256+k]=Wr
        g_Bh[n * 512 + k] = hr;               g_Bl[n * 512 + k] = lr;
        g_Bh[n * 512 + 256 + k] = nhi;        g_Bl[n * 512 + 256 + k] = nli;
        g_Bh[(256 + n) * 512 + k] = hi;       g_Bl[(256 + n) * 512 + k] = li;
        g_Bh[(256 + n) * 512 + 256 + k] = hr; g_Bl[(256 + n) * 512 + 256 + k] = lr;
    }
}

// ---------------- kernel 2.5: no-op spacer (aligns ncu capture slot onto gemm) ----------------
__global__ void probe_kernel() {}

// ---------------- kernel 3: tcgen05 bf16-split GEMM (sm_103a only) ----------------
#define KC 32
#define SMEM_TMEM 0
#define MB_FULL(s)  (16 + (s) * 8)
#define MB_EMPTY(s) (32 + (s) * 8)
#define MB_DONE     48
#define STAGE_SZ    81920
#define STAGE_BASE(s) (1024 + (s) * STAGE_SZ)
#define A_HI_OFF 0
#define A_LO_OFF 8192
#define B_HI_OFF 16384
#define B_LO_OFF 49152
#define SMEM_TOTAL (1024 + 2 * STAGE_SZ)

__global__ __launch_bounds__(256, 1)
void gemm_tc_kernel(const float* __restrict__ xre, const float* __restrict__ xim,
                    float* __restrict__ out) {
#if HAS_TC
    extern __shared__ char smem[];
    const uint32_t sb = smem_u32(smem);
    int tid = threadIdx.x, wid = tid >> 5, lane = tid & 31;
    int m0 = blockIdx.x * 128;

    if (wid == 4) TCGEN05_ALLOC(sb + SMEM_TMEM, 512);
    if (tid == 0) {
        MBARRIER_INIT(sb + MB_FULL(0), 7);
        MBARRIER_INIT(sb + MB_FULL(1), 7);
        MBARRIER_INIT(sb + MB_EMPTY(0), 1);
        MBARRIER_INIT(sb + MB_EMPTY(1), 1);
        MBARRIER_INIT(sb + MB_DONE, 1);
    }
    __syncthreads();
    uint32_t tmem;
    asm volatile("ld.shared.b32 %0, [%1];" : "=r"(tmem) : "r"(sb + SMEM_TMEM));

    if (wid < 4) {
        // ---- A producer (coalesced): per stage load X[m0:m0+128, kc:kc+32] fp32,
        // convert to bf16 hi/lo, STS SW64. Thread t, iter j: group g=j*128+t,
        // row r=g>>3, float4 idx f4=g&7 -> warp LDG touches 4 lines only.
        for (int it = 0; it < 16; ++it) {
            int s = it & 1;
            if (it >= 2) MBARRIER_WAIT_PARITY(sb + MB_EMPTY(s), ((it >> 1) - 1) & 1);
            const float* plane = (it < 8) ? xre : xim;
            int kc = (it & 7) * KC;
            uint32_t ahi = sb + STAGE_BASE(s) + A_HI_OFF;
            uint32_t alo = sb + STAGE_BASE(s) + A_LO_OFF;
#pragma unroll
            for (int j = 0; j < 8; ++j) {
                int g = j * 128 + tid;
                int r = g >> 3, f4 = g & 7;
                float4 v = *(const float4*)(plane + (size_t)(m0 + r) * NN + kc + f4 * 4);
                BU h0, h1, l0, l1;
                h0.h = __floats2bfloat162_rn(v.x, v.y);
                h1.h = __floats2bfloat162_rn(v.z, v.w);
                float2 f0 = __bfloat1622float2(h0.h), f1 = __bfloat1622float2(h1.h);
                l0.h = __floats2bfloat162_rn(v.x - f0.x, v.y - f0.y);
                l1.h = __floats2bfloat162_rn(v.z - f1.x, v.w - f1.y);
                uint32_t off = SWZ64((uint32_t)(r * 64 + f4 * 8));
                asm volatile("st.shared.v2.b32 [%0], {%1,%2};" :: "r"(ahi + off), "r"(h0.u), "r"(h1.u) : "memory");
                asm volatile("st.shared.v2.b32 [%0], {%1,%2};" :: "r"(alo + off), "r"(l0.u), "r"(l1.u) : "memory");
            }
            FENCE_ASYNC_SHARED();
            __syncwarp();
            if (lane == 0) MBARRIER_ARRIVE(sb + MB_FULL(s));
        }
    } else if (wid >= 5) {
        // ---- B producer: warps 5-7 cp.async g_Bh/g_Bl chunks (SW64)
        int tb = (wid - 5) * 32 + lane;  // 0..95
        const char* srch = (const char*)g_Bh;
        const char* srcl = (const char*)g_Bl;
        for (int it = 0; it < 16; ++it) {
            int s = it & 1;
            if (it >= 2) MBARRIER_WAIT_PARITY(sb + MB_EMPTY(s), ((it >> 1) - 1) & 1);
            int kb = it * (KC * 2);  // byte offset of this k-chunk within a 1024B row
            uint32_t bbase = sb + STAGE_BASE(s);
            for (int g = tb; g < 4096; g += 96) {
                int buf = g >> 11;
                int gg = g & 2047;
                int n = gg >> 2, gc = gg & 3;
                const char* src = (buf ? srcl : srch) + n * 1024 + kb + gc * 16;
                uint32_t dst = bbase + (buf ? B_LO_OFF : B_HI_OFF) + SWZ64((uint32_t)(n * 64 + gc * 16));
                asm volatile("cp.async.cg.shared.global [%0], [%1], 16;" :: "r"(dst), "l"(src) : "memory");
            }
            asm volatile("cp.async.commit_group;" ::: "memory");
            asm volatile("cp.async.wait_group 0;" ::: "memory");
            FENCE_ASYNC_SHARED();
            __syncwarp();
            if (lane == 0) MBARRIER_ARRIVE(sb + MB_FULL(s));
        }
    } else {
        // ---- MMA warp (wid == 4)
        const uint32_t IDESC = (1u << 4) | (1u << 7) | (1u << 10) | (32u << 17) | (8u << 24);
        for (int it = 0; it < 16; ++it) {
            int s = it & 1;
            MBARRIER_WAIT_PARITY(sb + MB_FULL(s), (it >> 1) & 1);
            if (elect_one_pred()) {
                uint32_t stage = sb + STAGE_BASE(s);
                uint64_t ah = make_desc_sw64(stage + A_HI_OFF);
                uint64_t al = make_desc_sw64(stage + A_LO_OFF);
                uint64_t bh = make_desc_sw64(stage + B_HI_OFF);
                uint64_t bl = make_desc_sw64(stage + B_LO_OFF);
#pragma unroll
                for (int seg = 0; seg < 3; ++seg) {
                    uint64_t ad = (seg == 2) ? al : ah;
                    uint64_t bd = (seg == 1) ? bl : bh;
#pragma unroll
                    for (int kk = 0; kk < 2; ++kk) {
#pragma unroll
                        for (int nh = 0; nh < 2; ++nh) {
                            uint32_t en = !(it == 0 && seg == 0 && kk == 0);
                            mma_f16_ss_cg1(tmem + nh * 256, ad + kk * 2,
                                           bd + (uint64_t)nh * 1024 + kk * 2, IDESC, en);
                        }
                    }
                }
                TCGEN05_COMMIT((it == 15) ? (sb + MB_DONE) : (sb + MB_EMPTY(s)));
            }
        }
    }

    // ---- epilogue: WG0 -> re plane (cols 0-255), WG1 -> im plane (cols 256-511)
    MBARRIER_WAIT_PARITY(sb + MB_DONE, 0);
    TCGEN05_FENCE_AFTER();
    {
        int wg = tid >> 7;
        int wt = tid & 127;
        int m = m0 + wt;
        float* dst = out + (size_t)wg * BB * NN + (size_t)m * NN;
        uint32_t colbase = tmem + wg * 256;
#pragma unroll
        for (int c = 0; c < 8; ++c) {
            uint32_t r[32];
            TCGEN05_LD_32X32B_X32(r, colbase + c * 32);
            TCGEN05_WAIT_LD();
            float4* d4 = (float4*)(dst + c * 32);
#pragma unroll
            for (int q = 0; q < 8; ++q)
                d4[q] = make_float4(__uint_as_float(r[4 * q]), __uint_as_float(r[4 * q + 1]),
                                    __uint_as_float(r[4 * q + 2]), __uint_as_float(r[4 * q + 3]));
        }
    }
    __syncthreads();
    if (wid == 4) {
        TCGEN05_RELINQ();
        TCGEN05_DEALLOC(tmem, 512);
    }
#endif  // HAS_TC
}

// ---------------- launch ----------------
extern "C" void kernel_launch(void* const* d_in, const int* in_sizes, int n_in,
                              void* d_out, int out_size) {
    const float* x_re  = (const float*)d_in[0];
    const float* x_im  = (const float*)d_in[1];
    const float* theta = (const float*)d_in[2];
    const float* phi   = (const float*)d_in[3];
    const float* gamma = (const float*)d_in[4];
    float* out = (float*)d_out;

    cudaFuncSetAttribute(gemm_tc_kernel, cudaFuncAttributeMaxDynamicSharedMemorySize, SMEM_TOTAL);

    coeff_kernel<<<LL, NN>>>(theta, phi);
    build_w_kernel<<<NN / RB, NN>>>(gamma);
    probe_kernel<<<1, 32>>>();
    gemm_tc_kernel<<<BB / 128, 256, SMEM_TOTAL>>>(x_re, x_im, out);
}